// round 2
// baseline (speedup 1.0000x reference)
#include <cuda_runtime.h>
#include <cuda_bf16.h>
#include <math.h>

#define D 512
#define B_GRAPHS 64
#define N_NODES 131072      // 64 * 2048
#define MAX_NODES 2048
#define FILL_VAL (-1e9f)

// Scratch (no allocations allowed)
__device__ float g_pn[B_GRAPHS * D];
__device__ int   g_start[B_GRAPHS];

// ---------------------------------------------------------------------------
// Kernel 1: pn = graph_attr @ W^T + b   (64 x 512, K = 512)
// Tiled: 16 graphs x 16 outputs per block, K staged in 128-wide chunks.
// grid = (32 jtiles, 4 gtiles), 256 threads.
// ---------------------------------------------------------------------------
__global__ void pn_gemm_kernel(const float* __restrict__ ga,
                               const float* __restrict__ W,
                               const float* __restrict__ bias) {
    __shared__ float ga_s[16][513];   // padded: avoid bank conflicts
    __shared__ float w_s[16][129];

    const int j0 = blockIdx.x * 16;
    const int g0 = blockIdx.y * 16;
    const int tid = threadIdx.x;

    // Load 16 graph_attr rows (16 x 512 floats) via float4, scalar smem stores
    for (int v = tid; v < 16 * 128; v += 256) {
        int r = v >> 7;          // row 0..15
        int c = v & 127;         // float4 col 0..127
        float4 val = reinterpret_cast<const float4*>(ga + (size_t)(g0 + r) * D)[c];
        ga_s[r][c * 4 + 0] = val.x;
        ga_s[r][c * 4 + 1] = val.y;
        ga_s[r][c * 4 + 2] = val.z;
        ga_s[r][c * 4 + 3] = val.w;
    }

    const int j = tid & 15;
    const int g = tid >> 4;
    float acc = 0.0f;

    for (int kc = 0; kc < 4; kc++) {
        __syncthreads();
        // Load W chunk: rows j0..j0+15, cols kc*128..kc*128+127  (512 float4)
        for (int v = tid; v < 512; v += 256) {
            int r = v >> 5;      // row 0..15
            int c = v & 31;      // float4 col 0..31
            float4 val = reinterpret_cast<const float4*>(
                W + (size_t)(j0 + r) * D + kc * 128)[c];
            w_s[r][c * 4 + 0] = val.x;
            w_s[r][c * 4 + 1] = val.y;
            w_s[r][c * 4 + 2] = val.z;
            w_s[r][c * 4 + 3] = val.w;
        }
        __syncthreads();
        const int kb = kc * 128;
#pragma unroll 16
        for (int k = 0; k < 128; k++) {
            acc += ga_s[g][kb + k] * w_s[j][k];
        }
    }

    g_pn[(size_t)(g0 + g) * D + (j0 + j)] = acc + bias[j0 + j];
}

// ---------------------------------------------------------------------------
// Kernel 2: init output to FILL and compute per-graph segment starts
// (general for any sorted batch; out_size == N_NODES here)
// ---------------------------------------------------------------------------
__global__ void fill_starts_kernel(const int* __restrict__ batch,
                                   float* __restrict__ out) {
    int i = blockIdx.x * blockDim.x + threadIdx.x;
    if (i >= N_NODES) return;
    out[i] = FILL_VAL;
    int bi = batch[i];
    if (i == 0 || batch[i - 1] != bi) {
        g_start[bi] = i;
    }
}

// ---------------------------------------------------------------------------
// Kernel 3: main fused kernel — one warp per node.
// sim = -sqrt(sum_d (x[i,d] - pn[g,d])^2) / temp ; scatter to dense position.
// ---------------------------------------------------------------------------
__global__ void node_sim_kernel(const float* __restrict__ x,
                                const int* __restrict__ batch,
                                const float* __restrict__ temp,
                                float* __restrict__ out) {
    const int warp = (blockIdx.x * blockDim.x + threadIdx.x) >> 5;
    const int lane = threadIdx.x & 31;
    if (warp >= N_NODES) return;

    const int g = batch[warp];

    const float4* __restrict__ xr =
        reinterpret_cast<const float4*>(x + (size_t)warp * D);
    const float4* __restrict__ pr =
        reinterpret_cast<const float4*>(g_pn + (size_t)g * D);

    float acc = 0.0f;
#pragma unroll
    for (int k = 0; k < 4; k++) {
        float4 xv = xr[lane + 32 * k];
        float4 pv = pr[lane + 32 * k];
        float d0 = xv.x - pv.x;
        float d1 = xv.y - pv.y;
        float d2 = xv.z - pv.z;
        float d3 = xv.w - pv.w;
        acc += d0 * d0 + d1 * d1 + d2 * d2 + d3 * d3;
    }

#pragma unroll
    for (int o = 16; o > 0; o >>= 1)
        acc += __shfl_xor_sync(0xFFFFFFFFu, acc, o);

    if (lane == 0) {
        int pos = warp - g_start[g];
        out[(size_t)g * MAX_NODES + pos] = -sqrtf(acc) / temp[0];
    }
}

// ---------------------------------------------------------------------------
extern "C" void kernel_launch(void* const* d_in, const int* in_sizes, int n_in,
                              void* d_out, int out_size) {
    const float* x     = (const float*)d_in[0];   // [N, D]
    const float* ga    = (const float*)d_in[1];   // [B, D]
    const int*   batch = (const int*)d_in[2];     // [N]
    const float* W     = (const float*)d_in[3];   // [D, D]
    const float* bias  = (const float*)d_in[4];   // [D]
    const float* temp  = (const float*)d_in[5];   // [1]
    float* out = (float*)d_out;                   // [B, MAX_NODES, 1]

    pn_gemm_kernel<<<dim3(32, 4), 256>>>(ga, W, bias);
    fill_starts_kernel<<<(N_NODES + 255) / 256, 256>>>(batch, out);
    node_sim_kernel<<<N_NODES / 8, 256>>>(x, batch, temp, out);
}

// round 3
// speedup vs baseline: 1.0780x; 1.0780x over previous
#include <cuda_runtime.h>
#include <cuda_bf16.h>
#include <math.h>

#define D 512
#define B_GRAPHS 64
#define N_NODES 131072      // 64 * 2048
#define MAX_NODES 2048
#define FILL_VAL (-1e9f)

#define GT 8                // graphs per warp tile
#define JT 8                // outputs per warp tile
#define GEMM_BLOCKS 64      // 64 blocks * 8 warps = 512 warps = (64/8)*(512/8)
#define FILL_BLOCKS 512     // 512 * 256 = 131072 threads

// Scratch (no allocations allowed)
__device__ float g_pn[B_GRAPHS * D];
__device__ int   g_start[B_GRAPHS];

// ---------------------------------------------------------------------------
// Kernel 1 (fused prologue):
//   blocks [0, 64):    pn = graph_attr @ W^T + b via warp-level 8x8 register
//                      tiles, K split across lanes, shuffle reduction.
//   blocks [64, 576):  out[i] = FILL, and record sorted-segment starts.
// ---------------------------------------------------------------------------
__global__ void prologue_kernel(const float* __restrict__ ga,
                                const float* __restrict__ W,
                                const float* __restrict__ bias,
                                const int* __restrict__ batch,
                                float* __restrict__ out) {
    if (blockIdx.x < GEMM_BLOCKS) {
        const int w    = blockIdx.x * 8 + (threadIdx.x >> 5);  // 0..511
        const int lane = threadIdx.x & 31;
        const int g0   = (w >> 6) * GT;        // 0,8,...,56
        const int j0   = (w & 63) * JT;        // 0,8,...,504

        const float4* __restrict__ ga4 = reinterpret_cast<const float4*>(ga);
        const float4* __restrict__ W4  = reinterpret_cast<const float4*>(W);

        float acc[GT][JT];
#pragma unroll
        for (int gg = 0; gg < GT; gg++)
#pragma unroll
            for (int jj = 0; jj < JT; jj++) acc[gg][jj] = 0.0f;

#pragma unroll
        for (int t = 0; t < 4; t++) {
            const int f = lane + 32 * t;       // float4 index within row (0..127)
            float4 a[GT];
#pragma unroll
            for (int gg = 0; gg < GT; gg++)
                a[gg] = ga4[(g0 + gg) * 128 + f];
#pragma unroll
            for (int jj = 0; jj < JT; jj++) {
                float4 wv = W4[(j0 + jj) * 128 + f];
#pragma unroll
                for (int gg = 0; gg < GT; gg++) {
                    acc[gg][jj] += a[gg].x * wv.x + a[gg].y * wv.y
                                 + a[gg].z * wv.z + a[gg].w * wv.w;
                }
            }
        }

        // cross-lane reduction (K partials)
#pragma unroll
        for (int gg = 0; gg < GT; gg++)
#pragma unroll
            for (int jj = 0; jj < JT; jj++) {
#pragma unroll
                for (int o = 16; o > 0; o >>= 1)
                    acc[gg][jj] += __shfl_xor_sync(0xFFFFFFFFu, acc[gg][jj], o);
            }

        if (lane == 0) {
#pragma unroll
            for (int jj = 0; jj < JT; jj++) {
                const float bj = bias[j0 + jj];
#pragma unroll
                for (int gg = 0; gg < GT; gg++)
                    g_pn[(g0 + gg) * D + j0 + jj] = acc[gg][jj] + bj;
            }
        }
    } else {
        const int i = (blockIdx.x - GEMM_BLOCKS) * 256 + threadIdx.x;
        if (i < N_NODES) {
            out[i] = FILL_VAL;
            const int bi = batch[i];
            if (i == 0 || batch[i - 1] != bi) g_start[bi] = i;
        }
    }
}

// ---------------------------------------------------------------------------
// Kernel 2: main fused kernel — one warp per node.
// sim = -sqrt(sum_d (x[i,d] - pn[g,d])^2) / temp ; scatter to dense position.
// ---------------------------------------------------------------------------
__global__ void node_sim_kernel(const float* __restrict__ x,
                                const int* __restrict__ batch,
                                const float* __restrict__ temp,
                                float* __restrict__ out) {
    const int warp = (blockIdx.x * blockDim.x + threadIdx.x) >> 5;
    const int lane = threadIdx.x & 31;
    if (warp >= N_NODES) return;

    const int g = batch[warp];

    const float4* __restrict__ xr =
        reinterpret_cast<const float4*>(x + (size_t)warp * D);
    const float4* __restrict__ pr =
        reinterpret_cast<const float4*>(g_pn + (size_t)g * D);

    float acc = 0.0f;
#pragma unroll
    for (int k = 0; k < 4; k++) {
        float4 xv = __ldcs(&xr[lane + 32 * k]);   // streaming: no reuse of x
        float4 pv = pr[lane + 32 * k];            // hot in L1/L2
        float d0 = xv.x - pv.x;
        float d1 = xv.y - pv.y;
        float d2 = xv.z - pv.z;
        float d3 = xv.w - pv.w;
        acc += d0 * d0 + d1 * d1 + d2 * d2 + d3 * d3;
    }

#pragma unroll
    for (int o = 16; o > 0; o >>= 1)
        acc += __shfl_xor_sync(0xFFFFFFFFu, acc, o);

    if (lane == 0) {
        int pos = warp - g_start[g];
        out[(size_t)g * MAX_NODES + pos] = -sqrtf(acc) / temp[0];
    }
}

// ---------------------------------------------------------------------------
extern "C" void kernel_launch(void* const* d_in, const int* in_sizes, int n_in,
                              void* d_out, int out_size) {
    const float* x     = (const float*)d_in[0];   // [N, D]
    const float* ga    = (const float*)d_in[1];   // [B, D]
    const int*   batch = (const int*)d_in[2];     // [N]
    const float* W     = (const float*)d_in[3];   // [D, D]
    const float* bias  = (const float*)d_in[4];   // [D]
    const float* temp  = (const float*)d_in[5];   // [1]
    float* out = (float*)d_out;                   // [B, MAX_NODES, 1]

    prologue_kernel<<<GEMM_BLOCKS + FILL_BLOCKS, 256>>>(ga, W, bias, batch, out);
    node_sim_kernel<<<N_NODES / 8, 256>>>(x, batch, temp, out);
}

// round 4
// speedup vs baseline: 1.2634x; 1.1720x over previous
#include <cuda_runtime.h>
#include <cuda_bf16.h>
#include <math.h>

#define D 512
#define B_GRAPHS 64
#define N_NODES 131072      // 64 * 2048
#define MAX_NODES 2048
#define FILL_VAL (-1e9f)

#define GT 8                // graphs per warp tile
#define JT 8                // outputs per warp tile
#define GEMM_BLOCKS 64      // 64 blocks * 8 warps = 512 warps
#define FILL_BLOCKS 512

// Scratch (no allocations allowed)
__device__ float g_pn[B_GRAPHS * D];
__device__ int   g_start[B_GRAPHS];

// ---------------------------------------------------------------------------
// Fused prologue:
//   blocks [0,64):   pn = graph_attr @ W^T + b. Warp computes 8x8 tile with
//                    K split across lanes; distributed butterfly reduce
//                    (62 SHFLs instead of 320), distributed stores.
//   blocks [64,576): out[i] = FILL + sorted-segment starts.
// ---------------------------------------------------------------------------
__global__ void prologue_kernel(const float* __restrict__ ga,
                                const float* __restrict__ W,
                                const float* __restrict__ bias,
                                const int* __restrict__ batch,
                                float* __restrict__ out) {
    if (blockIdx.x < GEMM_BLOCKS) {
        const int w    = blockIdx.x * 8 + (threadIdx.x >> 5);  // 0..511
        const int lane = threadIdx.x & 31;
        const int g0   = (w >> 6) * GT;        // 0,8,...,56
        const int j0   = (w & 63) * JT;        // 0,8,...,504

        const float4* __restrict__ ga4 = reinterpret_cast<const float4*>(ga);
        const float4* __restrict__ W4  = reinterpret_cast<const float4*>(W);

        float v[GT * JT];
#pragma unroll
        for (int i = 0; i < GT * JT; i++) v[i] = 0.0f;

#pragma unroll
        for (int t = 0; t < 4; t++) {
            const int f = lane + 32 * t;       // float4 index within row
            float4 a[GT];
#pragma unroll
            for (int gg = 0; gg < GT; gg++)
                a[gg] = ga4[(g0 + gg) * 128 + f];
#pragma unroll
            for (int jj = 0; jj < JT; jj++) {
                float4 wv = W4[(j0 + jj) * 128 + f];
#pragma unroll
                for (int gg = 0; gg < GT; gg++) {
                    v[gg * JT + jj] += a[gg].x * wv.x + a[gg].y * wv.y
                                     + a[gg].z * wv.z + a[gg].w * wv.w;
                }
            }
        }

        // Distributed butterfly reduce: 64 values -> 2 fully-reduced per lane.
        int cnt = GT * JT;
#pragma unroll
        for (int o = 1; o <= 16; o <<= 1) {
            cnt >>= 1;
            const bool hi = (lane & o) != 0;
#pragma unroll
            for (int i = 0; i < 32; i++) {      // bounded; only i<cnt active
                if (i >= cnt) break;
                float send = hi ? v[i] : v[i + cnt];
                float recv = __shfl_xor_sync(0xFFFFFFFFu, send, o);
                v[i] = (hi ? v[i + cnt] : v[i]) + recv;
            }
        }

        // lane owns orig indices 2*bitrev5(lane) + {0,1}
        const int R = ((lane & 1) << 4) | ((lane & 2) << 2) | (lane & 4)
                    | ((lane & 8) >> 2) | ((lane & 16) >> 4);
#pragma unroll
        for (int i = 0; i < 2; i++) {
            const int orig = 2 * R + i;
            const int gg = orig >> 3;
            const int jj = orig & 7;
            g_pn[(g0 + gg) * D + j0 + jj] = v[i] + bias[j0 + jj];
        }
    } else {
        const int i = (blockIdx.x - GEMM_BLOCKS) * 256 + threadIdx.x;
        if (i < N_NODES) {
            out[i] = FILL_VAL;
            const int bi = batch[i];
            if (i == 0 || batch[i - 1] != bi) g_start[bi] = i;
        }
    }
}

// ---------------------------------------------------------------------------
// Main kernel: half-warp (16 lanes) per node.
// Each lane: 8 float4 from x (streaming) + 8 float4 from pn (L1-hot),
// 4 independent accumulator chains, 4-level shuffle reduce.
// ---------------------------------------------------------------------------
__global__ void node_sim_kernel(const float* __restrict__ x,
                                const int* __restrict__ batch,
                                const float* __restrict__ temp,
                                float* __restrict__ out) {
    const int warp = (blockIdx.x * blockDim.x + threadIdx.x) >> 5;
    const int lane = threadIdx.x & 31;
    const int half = lane >> 4;          // 0 or 1
    const int s    = lane & 15;
    const int n    = warp * 2 + half;
    if (n >= N_NODES) return;

    const int g = batch[n];

    const float4* __restrict__ xr =
        reinterpret_cast<const float4*>(x) + (size_t)n * 128;
    const float4* __restrict__ pr =
        reinterpret_cast<const float4*>(g_pn) + (size_t)g * 128;

    float a0 = 0.0f, a1 = 0.0f, a2 = 0.0f, a3 = 0.0f;

#pragma unroll
    for (int wv = 0; wv < 2; wv++) {
        const int base = s + 64 * wv;    // 16 * (4*wv)
        float4 x0 = __ldcs(&xr[base +  0]);
        float4 x1 = __ldcs(&xr[base + 16]);
        float4 x2 = __ldcs(&xr[base + 32]);
        float4 x3 = __ldcs(&xr[base + 48]);
        float4 p0 = pr[base +  0];
        float4 p1 = pr[base + 16];
        float4 p2 = pr[base + 32];
        float4 p3 = pr[base + 48];

        float d;
        d = x0.x - p0.x; a0 += d * d;  d = x0.y - p0.y; a0 += d * d;
        d = x0.z - p0.z; a0 += d * d;  d = x0.w - p0.w; a0 += d * d;
        d = x1.x - p1.x; a1 += d * d;  d = x1.y - p1.y; a1 += d * d;
        d = x1.z - p1.z; a1 += d * d;  d = x1.w - p1.w; a1 += d * d;
        d = x2.x - p2.x; a2 += d * d;  d = x2.y - p2.y; a2 += d * d;
        d = x2.z - p2.z; a2 += d * d;  d = x2.w - p2.w; a2 += d * d;
        d = x3.x - p3.x; a3 += d * d;  d = x3.y - p3.y; a3 += d * d;
        d = x3.z - p3.z; a3 += d * d;  d = x3.w - p3.w; a3 += d * d;
    }

    float acc = (a0 + a1) + (a2 + a3);
#pragma unroll
    for (int o = 8; o > 0; o >>= 1)
        acc += __shfl_xor_sync(0xFFFFFFFFu, acc, o);

    if (s == 0) {
        int pos = n - g_start[g];
        out[(size_t)g * MAX_NODES + pos] = -sqrtf(acc) / temp[0];
    }
}

// ---------------------------------------------------------------------------
extern "C" void kernel_launch(void* const* d_in, const int* in_sizes, int n_in,
                              void* d_out, int out_size) {
    const float* x     = (const float*)d_in[0];   // [N, D]
    const float* ga    = (const float*)d_in[1];   // [B, D]
    const int*   batch = (const int*)d_in[2];     // [N]
    const float* W     = (const float*)d_in[3];   // [D, D]
    const float* bias  = (const float*)d_in[4];   // [D]
    const float* temp  = (const float*)d_in[5];   // [1]
    float* out = (float*)d_out;                   // [B, MAX_NODES, 1]

    prologue_kernel<<<GEMM_BLOCKS + FILL_BLOCKS, 256>>>(ga, W, bias, batch, out);
    node_sim_kernel<<<N_NODES / 16, 256>>>(x, batch, temp, out);
}